// round 10
// baseline (speedup 1.0000x reference)
#include <cuda_runtime.h>

// Signature-kernel MMD. fp32 FOLDED table (stores 0.25*inc - 1, read directly
// by the PDE FMA: no CVT, no reconstruct-FADD) packed into EXACTLY 16KB/task:
//   [guard 3 floats | O rows (coarse 1,3,..61) 31x65 | E rows (0,2,..62) 2078]
// = 4096 floats. WPC=2 -> CTA smem exactly 32KB -> 7 CTAs/SM (granularity-safe),
// 14 warps/SM, one wave. Carried-operand masking-free Goursat wavefront (R6).

#define BSZ 32
#define LEN 64
#define NTRI ((BSZ*(BSZ+1))/2)     // 528
#define NTASKS (2*NTRI + BSZ*BSZ)  // 2080
#define WPC 2
#define NBLK (NTASKS / WPC)        // 1040

#define RSF 65                     // row stride in floats
#define GUARDF 3
#define OSZF (31*RSF)              // 2015
#define ESZF 2078                  // E region (max read index 2077)
#define WFLOATS 4096               // exactly 16384 B per task

__device__ float g_partial[NTASKS];
__device__ unsigned int g_count;   // zero-init; reducer re-arms

__global__ void __launch_bounds__(32*WPC)
sig_kernel(const float* __restrict__ x, const float* __restrict__ y,
           float* __restrict__ out)
{
    extern __shared__ __align__(16) float smem[];
    const int lane = threadIdx.x & 31;
    const int wid  = threadIdx.x >> 5;
    const int task = blockIdx.x * WPC + wid;

    float* warpbase = smem + wid * WFLOATS;
    float* Ob = warpbase + GUARDF;        // idx 3
    float* Eb = Ob + OSZF;                // idx 2018

    // Zero own 16KB region: all stray PDE reads must return finite values.
    {
        uint4* z = reinterpret_cast<uint4*>(warpbase);
        #pragma unroll
        for (int i = lane; i < WFLOATS/4; i += 32)
            z[i] = make_uint4(0u, 0u, 0u, 0u);
    }

    // ---- decode task -> pair pointers + weight ----
    const float *pa, *pb;
    float weight;
    {
        int t = task;
        if (t < 2*NTRI) {
            const float* base = (t < NTRI) ? x : y;
            if (t >= NTRI) t -= NTRI;
            int a = 0;
            while (t >= (BSZ - a)) { t -= (BSZ - a); ++a; }
            int b = a + t;
            pa = base + a*(LEN*4);
            pb = base + b*(LEN*4);
            weight = (a == b ? 1.0f : 2.0f) * (1.0f/1024.0f);
        } else {
            t -= 2*NTRI;
            pa = x + (t >> 5)*(LEN*4);
            pb = y + (t & 31)*(LEN*4);
            weight = -2.0f/1024.0f;
        }
    }

    // ---- streaming RBF gram + folded second differences (fp32) ----
    const int j0 = lane << 1;
    const float4 b0 = __ldg(reinterpret_cast<const float4*>(pb + 4*j0));
    const float4 b1 = __ldg(reinterpret_cast<const float4*>(pb + 4*j0 + 4));

    float g0p, g1p;
    {
        float4 a = __ldg(reinterpret_cast<const float4*>(pa));
        float d0x=a.x-b0.x, d0y=a.y-b0.y, d0z=a.z-b0.z, d0w=a.w-b0.w;
        float d1x=a.x-b1.x, d1y=a.y-b1.y, d1z=a.z-b1.z, d1w=a.w-b1.w;
        g0p = __expf(-0.5f*(d0x*d0x + d0y*d0y + d0z*d0z + d0w*d0w));
        g1p = __expf(-0.5f*(d1x*d1x + d1y*d1y + d1z*d1z + d1w*d1w));
    }
    #pragma unroll 4
    for (int u = 1; u < LEN; ++u) {
        float4 a = __ldg(reinterpret_cast<const float4*>(pa + 4*u));
        float d0x=a.x-b0.x, d0y=a.y-b0.y, d0z=a.z-b0.z, d0w=a.w-b0.w;
        float d1x=a.x-b1.x, d1y=a.y-b1.y, d1z=a.z-b1.z, d1w=a.w-b1.w;
        float g0 = __expf(-0.5f*(d0x*d0x + d0y*d0y + d0z*d0z + d0w*d0w));
        float g1 = __expf(-0.5f*(d1x*d1x + d1y*d1y + d1z*d1z + d1w*d1w));
        float t0 = g0 - g0p;
        float t1 = g1 - g1p;
        float tn = __shfl_down_sync(0xffffffffu, t0, 1);
        float r0 = fmaf(0.25f, t1 - t0, -1.0f);    // folded: 0.25*inc - 1
        float r1 = fmaf(0.25f, tn - t1, -1.0f);
        int v = u - 1;
        bool odd = (v & 1);
        float* row = (odd ? Ob : Eb) + (v >> 1) * RSF;
        row[j0] = r0;
        // E row 31 col 63 (lane31, even v=62) would write past the region; it
        // is a never-read pad -> clip. All other (row,col 63) writes stay inside.
        if (odd | (lane != 31)) row[j0 + 1] = r1;
        g0p = g0; g1p = g1;
    }
    __syncwarp();

    // ---- Goursat PDE, antidiagonal wavefront, carried-operand loop ----
    // Lane holds cells i = 4*lane + k. Carried: a0A(m)=a0B(m-1), a2(m)=a1(m-1),
    // sh2(m)=sh1b(m-1). Table values are folded -> used directly in the FMA.
    const int L = lane;
    const bool isL0 = (L == 0);
    const float* p0 = Ob + ((L == 0) ? 0 : (63*L - 65));
    const float* p1 = Eb + 63*L;
    const float* p3 = Ob + 63*L - 1;

    float A0 = isL0 ? 1.f : 0.f, A1 = 0.f, A2 = 0.f, A3 = 0.f;   // diag 0
    float B0 = A0, B1 = A0, B2 = 0.f, B3 = 0.f;                  // diag 1

    float a0A = p0[0];
    float a2  = p1[-1];          // p2[0] == p1[-1]
    float sh2 = 0.0f;            // shfl(A3_init) == 0

    #pragma unroll 5
    for (int m = 0; m < 125; ++m) {
        float sh1 = __shfl_up_sync(0xffffffffu, B3, 1);
        float a0B = p0[m+1];
        float a1  = p1[m];
        float a3  = p3[m];
        // diag d = 2m+2
        float v0 = fmaf(sh2, a0A, sh1) + B0;  if (isL0) v0 = 1.f;
        float v1 = fmaf(A0, a1, B0) + B1;
        float v2 = fmaf(A1, a2, B1) + B2;
        float v3 = fmaf(A2, a3, B2) + B3;
        // diag d+1 = 2m+3
        float sh1b = __shfl_up_sync(0xffffffffu, v3, 1);
        float w0 = fmaf(sh1, a0B, sh1b) + v0; if (isL0) w0 = 1.f;
        float w1 = fmaf(B0, a1, v0) + v1;
        float w2 = fmaf(B1, a1, v1) + v2;
        float w3 = fmaf(B2, a3, v2) + v3;
        A0 = v0; A1 = v1; A2 = v2; A3 = v3;
        B0 = w0; B1 = w1; B2 = w2; B3 = w3;
        a0A = a0B; a2 = a1; sh2 = sh1b;     // carry
    }
    // final diag 252: cell k=2 on lane 31 (i=126, j=126); inc = carried a2.
    float f2 = fmaf(A1, a2, B1) + B2;
    float res = __shfl_sync(0xffffffffu, f2, 31);
    if (lane == 0) g_partial[task] = res * weight;

    // ---- last-block deterministic reduction ----
    // Ticket broadcast via dynamic smem (guard word; PDE is done, guard free).
    // NO static __shared__: CTA smem must stay exactly 32KB for 7 CTAs/SM.
    __threadfence();
    __syncthreads();
    unsigned int* ticket_slot = reinterpret_cast<unsigned int*>(smem);
    if (threadIdx.x == 0) *ticket_slot = atomicAdd(&g_count, 1u);
    __syncthreads();
    if (*ticket_slot == (unsigned)(gridDim.x - 1)) {
        double s = 0.0;
        for (int i = threadIdx.x; i < NTASKS; i += 32*WPC)
            s += (double)__ldcg(&g_partial[i]);
        double* ds = reinterpret_cast<double*>(smem + 64);
        ds[threadIdx.x] = s;
        __syncthreads();
        for (int w = (32*WPC)/2; w > 0; w >>= 1) {
            if (threadIdx.x < w) ds[threadIdx.x] += ds[threadIdx.x + w];
            __syncthreads();
        }
        if (threadIdx.x == 0) {
            out[0] = (float)ds[0];
            g_count = 0;                 // re-arm for next graph replay
        }
    }
}

extern "C" void kernel_launch(void* const* d_in, const int* in_sizes, int n_in,
                              void* d_out, int out_size)
{
    const float* x = (const float*)d_in[0];
    const float* y = (const float*)d_in[1];
    (void)in_sizes; (void)n_in; (void)out_size;

    cudaFuncSetAttribute(sig_kernel,
                         cudaFuncAttributePreferredSharedMemoryCarveout, 100);

    const size_t shmem = (size_t)WPC * WFLOATS * sizeof(float);  // 32768 B exact
    sig_kernel<<<NBLK, 32*WPC, shmem>>>(x, y, (float*)d_out);
}

// round 11
// speedup vs baseline: 1.2250x; 1.2250x over previous
#include <cuda_runtime.h>

// Signature-kernel MMD. fp32 FOLDED table (0.25*inc - 1, consumed directly by
// the PDE FMA: zero CVT / reconstruct ops) packed with row stride 63 so a task
// fits in 15904 B:  [guard 4 | O: 31x63 odd coarse rows | E: 32x63 even rows].
// Lane step for all PDE streams = 61 (odd) => conflict-free LDS. WPC=2 ->
// CTA smem 31808 B; with the ~1KB/CTA driver reserve 7 CTAs/SM still fit ->
// 14 warps/SM, one wave (the R10 failure mode). Masking-free Goursat wavefront
// with carried operands (R6); last-block deterministic reduction.

#define BSZ 32
#define LEN 64
#define NTRI ((BSZ*(BSZ+1))/2)     // 528
#define NTASKS (2*NTRI + BSZ*BSZ)  // 2080
#define WPC 2
#define NBLK (NTASKS / WPC)        // 1040

#define RSF 63                     // row stride in floats
#define GUARDF 4
#define OSZF (31*RSF)              // 1953
#define ESZF (32*RSF)              // 2016
#define WFLOATS 3976               // 4+1953+2016=3973, padded to x4 -> 15904 B

__device__ float g_partial[NTASKS];
__device__ unsigned int g_count;   // zero-init; reducer re-arms

__global__ void __launch_bounds__(32*WPC)
sig_kernel(const float* __restrict__ x, const float* __restrict__ y,
           float* __restrict__ out)
{
    extern __shared__ __align__(16) float smem[];
    const int lane = threadIdx.x & 31;
    const int wid  = threadIdx.x >> 5;
    const int task = blockIdx.x * WPC + wid;

    float* warpbase = smem + wid * WFLOATS;
    float* Ob = warpbase + GUARDF;        // odd coarse rows 1,3,..,61
    float* Eb = Ob + OSZF;                // even coarse rows 0,2,..,62

    // Zero own region (incl. guard): every stray PDE read must be finite.
    {
        uint4* z = reinterpret_cast<uint4*>(warpbase);
        #pragma unroll
        for (int i = lane; i < WFLOATS/4; i += 32)
            z[i] = make_uint4(0u, 0u, 0u, 0u);
    }

    // ---- decode task -> pair pointers + weight ----
    const float *pa, *pb;
    float weight;
    {
        int t = task;
        if (t < 2*NTRI) {
            const float* base = (t < NTRI) ? x : y;
            if (t >= NTRI) t -= NTRI;
            int a = 0;
            while (t >= (BSZ - a)) { t -= (BSZ - a); ++a; }
            int b = a + t;
            pa = base + a*(LEN*4);
            pb = base + b*(LEN*4);
            weight = (a == b ? 1.0f : 2.0f) * (1.0f/1024.0f);
        } else {
            t -= 2*NTRI;
            pa = x + (t >> 5)*(LEN*4);
            pb = y + (t & 31)*(LEN*4);
            weight = -2.0f/1024.0f;
        }
    }

    // ---- streaming RBF gram + folded second differences (fp32) ----
    const int j0 = lane << 1;
    const float4 b0 = __ldg(reinterpret_cast<const float4*>(pb + 4*j0));
    const float4 b1 = __ldg(reinterpret_cast<const float4*>(pb + 4*j0 + 4));

    float g0p, g1p;
    {
        float4 a = __ldg(reinterpret_cast<const float4*>(pa));
        float d0x=a.x-b0.x, d0y=a.y-b0.y, d0z=a.z-b0.z, d0w=a.w-b0.w;
        float d1x=a.x-b1.x, d1y=a.y-b1.y, d1z=a.z-b1.z, d1w=a.w-b1.w;
        g0p = __expf(-0.5f*(d0x*d0x + d0y*d0y + d0z*d0z + d0w*d0w));
        g1p = __expf(-0.5f*(d1x*d1x + d1y*d1y + d1z*d1z + d1w*d1w));
    }
    #pragma unroll 4
    for (int u = 1; u < LEN; ++u) {
        float4 a = __ldg(reinterpret_cast<const float4*>(pa + 4*u));
        float d0x=a.x-b0.x, d0y=a.y-b0.y, d0z=a.z-b0.z, d0w=a.w-b0.w;
        float d1x=a.x-b1.x, d1y=a.y-b1.y, d1z=a.z-b1.z, d1w=a.w-b1.w;
        float g0 = __expf(-0.5f*(d0x*d0x + d0y*d0y + d0z*d0z + d0w*d0w));
        float g1 = __expf(-0.5f*(d1x*d1x + d1y*d1y + d1z*d1z + d1w*d1w));
        float t0 = g0 - g0p;
        float t1 = g1 - g1p;
        float tn = __shfl_down_sync(0xffffffffu, t0, 1);
        float r0 = fmaf(0.25f, t1 - t0, -1.0f);    // folded: 0.25*inc - 1
        float r1 = fmaf(0.25f, tn - t1, -1.0f);
        int v = u - 1;
        float* row = ((v & 1) ? Ob : Eb) + (v >> 1) * RSF;
        row[j0] = r0;                              // cols 0..62 real
        if (lane != 31) row[j0 + 1] = r1;          // col 63 doesn't exist: clip
        g0p = g0; g1p = g1;
    }
    __syncwarp();

    // ---- Goursat PDE, antidiagonal wavefront, carried-operand loop ----
    // Lane holds cells i = 4*lane + k. Stride-63 pointer bases (lane step 61):
    //   k0: O row L-1, col m-2L   -> p0 = Ob + 61L - 63   (L=0: clamped, boundary)
    //   k1: E row L,   col m-2L   -> p1 = Eb + 61L
    //   k2: E row L,   col m-2L-1 -> carried a2 = a1(m-1)
    //   k3: O row L,   col m-2L-1 -> p3 = Ob + 61L - 1
    // Carried: a0A(m)=a0B(m-1), a2(m)=a1(m-1), sh2(m)=sh1b(m-1).
    const int L = lane;
    const bool isL0 = (L == 0);
    const float* p0 = (L == 0) ? Ob : (Ob + 61*L - 63);
    const float* p1 = Eb + 61*L;
    const float* p3 = Ob + 61*L - 1;

    float A0 = isL0 ? 1.f : 0.f, A1 = 0.f, A2 = 0.f, A3 = 0.f;   // diag 0
    float B0 = A0, B1 = A0, B2 = 0.f, B3 = 0.f;                  // diag 1

    float a0A = p0[0];
    float a2  = p1[-1];          // p2[0] == p1[-1] (finite; operand of zero)
    float sh2 = 0.0f;            // shfl(A3_init) == 0

    #pragma unroll 5
    for (int m = 0; m < 125; ++m) {
        float sh1 = __shfl_up_sync(0xffffffffu, B3, 1);
        float a0B = p0[m+1];
        float a1  = p1[m];
        float a3  = p3[m];
        // diag d = 2m+2
        float v0 = fmaf(sh2, a0A, sh1) + B0;  if (isL0) v0 = 1.f;
        float v1 = fmaf(A0, a1, B0) + B1;
        float v2 = fmaf(A1, a2, B1) + B2;
        float v3 = fmaf(A2, a3, B2) + B3;
        // diag d+1 = 2m+3
        float sh1b = __shfl_up_sync(0xffffffffu, v3, 1);
        float w0 = fmaf(sh1, a0B, sh1b) + v0; if (isL0) w0 = 1.f;
        float w1 = fmaf(B0, a1, v0) + v1;
        float w2 = fmaf(B1, a1, v1) + v2;
        float w3 = fmaf(B2, a3, v2) + v3;
        A0 = v0; A1 = v1; A2 = v2; A3 = v3;
        B0 = w0; B1 = w1; B2 = w2; B3 = w3;
        a0A = a0B; a2 = a1; sh2 = sh1b;     // carry
    }
    // final diag 252: cell k=2 on lane 31 (i=126, j=126); inc = carried a2.
    float f2 = fmaf(A1, a2, B1) + B2;
    float res = __shfl_sync(0xffffffffu, f2, 31);
    if (lane == 0) g_partial[task] = res * weight;

    // ---- last-block deterministic reduction ----
    // Ticket + scratch live in the (now free) dynamic smem: NO static __shared__
    // so the CTA footprint stays at exactly the dynamic 31808 B.
    __threadfence();
    __syncthreads();
    unsigned int* ticket_slot = reinterpret_cast<unsigned int*>(smem);
    if (threadIdx.x == 0) *ticket_slot = atomicAdd(&g_count, 1u);
    __syncthreads();
    if (*ticket_slot == (unsigned)(gridDim.x - 1)) {
        double s = 0.0;
        for (int i = threadIdx.x; i < NTASKS; i += 32*WPC)
            s += (double)__ldcg(&g_partial[i]);
        double* ds = reinterpret_cast<double*>(smem + 64);
        ds[threadIdx.x] = s;
        __syncthreads();
        for (int w = (32*WPC)/2; w > 0; w >>= 1) {
            if (threadIdx.x < w) ds[threadIdx.x] += ds[threadIdx.x + w];
            __syncthreads();
        }
        if (threadIdx.x == 0) {
            out[0] = (float)ds[0];
            g_count = 0;                 // re-arm for next graph replay
        }
    }
}

extern "C" void kernel_launch(void* const* d_in, const int* in_sizes, int n_in,
                              void* d_out, int out_size)
{
    const float* x = (const float*)d_in[0];
    const float* y = (const float*)d_in[1];
    (void)in_sizes; (void)n_in; (void)out_size;

    cudaFuncSetAttribute(sig_kernel,
                         cudaFuncAttributePreferredSharedMemoryCarveout, 100);

    const size_t shmem = (size_t)WPC * WFLOATS * sizeof(float);  // 31808 B
    sig_kernel<<<NBLK, 32*WPC, shmem>>>(x, y, (float*)d_out);
}

// round 12
// speedup vs baseline: 1.2279x; 1.0024x over previous
#include <cuda_runtime.h>

// Signature-kernel MMD. R11 base: fp32 folded table (0.25*inc - 1) at row
// stride 63 => 15904 B/task, WPC=2 => 31808 B/CTA => 7 CTAs/SM, 14 warps/SM,
// conflict-free LDS (lane step 61). Changes vs R11:
//   - zero ONLY guard+pad (audit: every PDE-readable byte is gram-written or guard)
//   - __launch_bounds__(64, 7): reg budget ~146 so ptxas can hoist PDE loads
//   - #pragma unroll 25 on the PDE loop (longer scheduling window)

#define BSZ 32
#define LEN 64
#define NTRI ((BSZ*(BSZ+1))/2)     // 528
#define NTASKS (2*NTRI + BSZ*BSZ)  // 2080
#define WPC 2
#define NBLK (NTASKS / WPC)        // 1040

#define RSF 63                     // row stride in floats
#define GUARDF 4
#define OSZF (31*RSF)              // 1953
#define ESZF (32*RSF)              // 2016
#define WFLOATS 3976               // 4+1953+2016=3973 -> padded to 15904 B

__device__ float g_partial[NTASKS];
__device__ unsigned int g_count;   // zero-init; reducer re-arms

__global__ void __launch_bounds__(32*WPC, 7)
sig_kernel(const float* __restrict__ x, const float* __restrict__ y,
           float* __restrict__ out)
{
    extern __shared__ __align__(16) float smem[];
    const int lane = threadIdx.x & 31;
    const int wid  = threadIdx.x >> 5;
    const int task = blockIdx.x * WPC + wid;

    float* warpbase = smem + wid * WFLOATS;
    float* Ob = warpbase + GUARDF;        // odd coarse rows 1,3,..,61
    float* Eb = Ob + OSZF;                // even coarse rows 0,2,..,62

    // Zero ONLY guard (read by p3 lane0 / p0 lane1) and tail pad. All other
    // PDE-readable bytes are fully written by the gram phase (audited per
    // stream: O and E are gap-free at stride 63; spills suppressed/in-pad).
    if (lane == 0) {
        reinterpret_cast<uint4*>(warpbase)[0]   = make_uint4(0u,0u,0u,0u);  // guard
        reinterpret_cast<uint4*>(warpbase)[993] = make_uint4(0u,0u,0u,0u);  // pad 3972..3975
    }

    // ---- decode task -> pair pointers + weight ----
    const float *pa, *pb;
    float weight;
    {
        int t = task;
        if (t < 2*NTRI) {
            const float* base = (t < NTRI) ? x : y;
            if (t >= NTRI) t -= NTRI;
            int a = 0;
            while (t >= (BSZ - a)) { t -= (BSZ - a); ++a; }
            int b = a + t;
            pa = base + a*(LEN*4);
            pb = base + b*(LEN*4);
            weight = (a == b ? 1.0f : 2.0f) * (1.0f/1024.0f);
        } else {
            t -= 2*NTRI;
            pa = x + (t >> 5)*(LEN*4);
            pb = y + (t & 31)*(LEN*4);
            weight = -2.0f/1024.0f;
        }
    }

    // ---- streaming RBF gram + folded second differences (fp32) ----
    const int j0 = lane << 1;
    const float4 b0 = __ldg(reinterpret_cast<const float4*>(pb + 4*j0));
    const float4 b1 = __ldg(reinterpret_cast<const float4*>(pb + 4*j0 + 4));

    float g0p, g1p;
    {
        float4 a = __ldg(reinterpret_cast<const float4*>(pa));
        float d0x=a.x-b0.x, d0y=a.y-b0.y, d0z=a.z-b0.z, d0w=a.w-b0.w;
        float d1x=a.x-b1.x, d1y=a.y-b1.y, d1z=a.z-b1.z, d1w=a.w-b1.w;
        g0p = __expf(-0.5f*(d0x*d0x + d0y*d0y + d0z*d0z + d0w*d0w));
        g1p = __expf(-0.5f*(d1x*d1x + d1y*d1y + d1z*d1z + d1w*d1w));
    }
    #pragma unroll 4
    for (int u = 1; u < LEN; ++u) {
        float4 a = __ldg(reinterpret_cast<const float4*>(pa + 4*u));
        float d0x=a.x-b0.x, d0y=a.y-b0.y, d0z=a.z-b0.z, d0w=a.w-b0.w;
        float d1x=a.x-b1.x, d1y=a.y-b1.y, d1z=a.z-b1.z, d1w=a.w-b1.w;
        float g0 = __expf(-0.5f*(d0x*d0x + d0y*d0y + d0z*d0z + d0w*d0w));
        float g1 = __expf(-0.5f*(d1x*d1x + d1y*d1y + d1z*d1z + d1w*d1w));
        float t0 = g0 - g0p;
        float t1 = g1 - g1p;
        float tn = __shfl_down_sync(0xffffffffu, t0, 1);
        float r0 = fmaf(0.25f, t1 - t0, -1.0f);    // folded: 0.25*inc - 1
        float r1 = fmaf(0.25f, tn - t1, -1.0f);
        int v = u - 1;
        float* row = ((v & 1) ? Ob : Eb) + (v >> 1) * RSF;
        row[j0] = r0;                              // cols 0..62 real
        if (lane != 31) row[j0 + 1] = r1;          // col 63 doesn't exist: clip
        g0p = g0; g1p = g1;
    }
    __syncwarp();

    // ---- Goursat PDE, antidiagonal wavefront, carried-operand loop ----
    // Lane holds cells i = 4*lane + k. Stride-63 pointer bases (lane step 61).
    // Carried: a0A(m)=a0B(m-1), a2(m)=a1(m-1), sh2(m)=sh1b(m-1).
    const int L = lane;
    const bool isL0 = (L == 0);
    const float* p0 = (L == 0) ? Ob : (Ob + 61*L - 63);
    const float* p1 = Eb + 61*L;
    const float* p3 = Ob + 61*L - 1;

    float A0 = isL0 ? 1.f : 0.f, A1 = 0.f, A2 = 0.f, A3 = 0.f;   // diag 0
    float B0 = A0, B1 = A0, B2 = 0.f, B3 = 0.f;                  // diag 1

    float a0A = p0[0];
    float a2  = p1[-1];          // p2[0] == p1[-1] (finite; operand of zero)
    float sh2 = 0.0f;            // shfl(A3_init) == 0

    #pragma unroll 25
    for (int m = 0; m < 125; ++m) {
        float sh1 = __shfl_up_sync(0xffffffffu, B3, 1);
        float a0B = p0[m+1];
        float a1  = p1[m];
        float a3  = p3[m];
        // diag d = 2m+2
        float v0 = fmaf(sh2, a0A, sh1) + B0;  if (isL0) v0 = 1.f;
        float v1 = fmaf(A0, a1, B0) + B1;
        float v2 = fmaf(A1, a2, B1) + B2;
        float v3 = fmaf(A2, a3, B2) + B3;
        // diag d+1 = 2m+3
        float sh1b = __shfl_up_sync(0xffffffffu, v3, 1);
        float w0 = fmaf(sh1, a0B, sh1b) + v0; if (isL0) w0 = 1.f;
        float w1 = fmaf(B0, a1, v0) + v1;
        float w2 = fmaf(B1, a1, v1) + v2;
        float w3 = fmaf(B2, a3, v2) + v3;
        A0 = v0; A1 = v1; A2 = v2; A3 = v3;
        B0 = w0; B1 = w1; B2 = w2; B3 = w3;
        a0A = a0B; a2 = a1; sh2 = sh1b;     // carry
    }
    // final diag 252: cell k=2 on lane 31 (i=126, j=126); inc = carried a2.
    float f2 = fmaf(A1, a2, B1) + B2;
    float res = __shfl_sync(0xffffffffu, f2, 31);
    if (lane == 0) g_partial[task] = res * weight;

    // ---- last-block deterministic reduction ----
    // Ticket + scratch in dynamic smem (no static __shared__: keep CTA smem
    // at exactly the dynamic 31808 B for 7 CTAs/SM).
    __threadfence();
    __syncthreads();
    unsigned int* ticket_slot = reinterpret_cast<unsigned int*>(smem);
    if (threadIdx.x == 0) *ticket_slot = atomicAdd(&g_count, 1u);
    __syncthreads();
    if (*ticket_slot == (unsigned)(gridDim.x - 1)) {
        double s = 0.0;
        for (int i = threadIdx.x; i < NTASKS; i += 32*WPC)
            s += (double)__ldcg(&g_partial[i]);
        double* ds = reinterpret_cast<double*>(smem + 64);
        ds[threadIdx.x] = s;
        __syncthreads();
        for (int w = (32*WPC)/2; w > 0; w >>= 1) {
            if (threadIdx.x < w) ds[threadIdx.x] += ds[threadIdx.x + w];
            __syncthreads();
        }
        if (threadIdx.x == 0) {
            out[0] = (float)ds[0];
            g_count = 0;                 // re-arm for next graph replay
        }
    }
}

extern "C" void kernel_launch(void* const* d_in, const int* in_sizes, int n_in,
                              void* d_out, int out_size)
{
    const float* x = (const float*)d_in[0];
    const float* y = (const float*)d_in[1];
    (void)in_sizes; (void)n_in; (void)out_size;

    cudaFuncSetAttribute(sig_kernel,
                         cudaFuncAttributePreferredSharedMemoryCarveout, 100);

    const size_t shmem = (size_t)WPC * WFLOATS * sizeof(float);  // 31808 B
    sig_kernel<<<NBLK, 32*WPC, shmem>>>(x, y, (float*)d_out);
}